// round 4
// baseline (speedup 1.0000x reference)
#include <cuda_runtime.h>
#include <cuda_fp16.h>
#include <math.h>

#define NN 50000
#define EPS_BN 1e-5f

// ---------------- scratch (device globals: allocation-free) ----------------
static __device__ float g_h1[(long long)NN * 256];      // x @ W1 (fp32, for sd1)
static __device__ __half g_h1h[(long long)NN * 256];    // fp16 copy for gather
static __device__ float g_out1[(long long)NN * 256];    // elu(bn(gat1))
static __device__ float g_h2[(long long)NN * 128];      // out1 @ W2 (fp32, for sd2)
static __device__ __half g_h2h[(long long)NN * 128];    // fp16 copy for gather
static __device__ float g_s1[NN * 4];
static __device__ float g_d1[NN * 4];
static __device__ float g_s2[NN * 4];
static __device__ float g_d2[NN * 4];
static __device__ int g_deg[NN];
static __device__ int g_cur[NN];
static __device__ int g_rowptr[NN + 1];
static __device__ int g_bsum[64];
static __device__ int g_col[900000];
static __device__ int g_is64;

__device__ __forceinline__ float lrelu(float x) { return x > 0.f ? x : 0.2f * x; }

// ---------------- edge dtype detection (int64 vs int32) ----------------
__global__ void detect_kernel(const int* __restrict__ e) {
    __shared__ int bad;
    if (threadIdx.x == 0) bad = 0;
    __syncthreads();
    if (e[2 * threadIdx.x + 1] != 0) bad = 1;
    __syncthreads();
    if (threadIdx.x == 0) g_is64 = bad ? 0 : 1;
}

__device__ __forceinline__ int eval_idx(const void* e, long long idx) {
    return g_is64 ? (int)((const long long*)e)[idx] : ((const int*)e)[idx];
}

// ---------------- CSR build ----------------
__global__ void zero_kernel() {
    int i = blockIdx.x * blockDim.x + threadIdx.x;
    if (i < NN) { g_deg[i] = 0; g_cur[i] = 0; }
}

__global__ void count_kernel(const void* __restrict__ e, int E, int EP) {
    int i = blockIdx.x * blockDim.x + threadIdx.x;
    if (i >= EP) return;
    int d = (i < E) ? eval_idx(e, (long long)E + i) : (i - E);
    atomicAdd(&g_deg[d], 1);
}

__global__ void __launch_bounds__(1024) scan_block_kernel() {
    __shared__ int sh[1024];
    int t = threadIdx.x;
    int i = blockIdx.x * 1024 + t;
    int v = (i < NN) ? g_deg[i] : 0;
    sh[t] = v;
    __syncthreads();
#pragma unroll
    for (int off = 1; off < 1024; off <<= 1) {
        int tv = (t >= off) ? sh[t - off] : 0;
        __syncthreads();
        sh[t] += tv;
        __syncthreads();
    }
    if (i < NN) g_rowptr[i] = sh[t] - v;
    if (t == 1023) g_bsum[blockIdx.x] = sh[1023];
}

__global__ void scan_sums_kernel(int nblk) {
    __shared__ int sh[64];
    int t = threadIdx.x;
    int v = (t < nblk) ? g_bsum[t] : 0;
    sh[t] = v;
    __syncthreads();
#pragma unroll
    for (int off = 1; off < 64; off <<= 1) {
        int tv = (t >= off) ? sh[t - off] : 0;
        __syncthreads();
        sh[t] += tv;
        __syncthreads();
    }
    if (t < nblk) g_bsum[t] = sh[t] - v;
    if (t == 63) g_rowptr[NN] = sh[63];
}

__global__ void __launch_bounds__(1024) scan_add_kernel() {
    int i = blockIdx.x * 1024 + threadIdx.x;
    if (i < NN) g_rowptr[i] += g_bsum[blockIdx.x];
}

__global__ void scatter_kernel(const void* __restrict__ e, int E, int EP) {
    int i = blockIdx.x * blockDim.x + threadIdx.x;
    if (i >= EP) return;
    int s, d;
    if (i < E) { s = eval_idx(e, i); d = eval_idx(e, (long long)E + i); }
    else       { s = i - E; d = s; }
    int pos = atomicAdd(&g_cur[d], 1);
    g_col[g_rowptr[d] + pos] = s;
}

// ---------------- SGEMM: C[M,Nc] = A[M,K] @ B[K,Nc], fp32 ----------------
// 128x128 tile, 8x8/thread, BK=16, 256 threads, double-buffered smem,
// packed fma.rn.f32x2, epilogue also writes fp16 copy Ch.
__global__ void __launch_bounds__(256) gemm_kernel(
    const float* __restrict__ A, const float* __restrict__ B, float* __restrict__ C,
    __half* __restrict__ Ch, int M, int K, int Nc)
{
    __shared__ float As[2][16][132];
    __shared__ float Bs[2][16][132];
    int tid = threadIdx.x;
    int tx = tid & 15, ty = tid >> 4;
    int row0 = blockIdx.y * 128;
    int col0 = blockIdx.x * 128;

    unsigned long long accp[8][4];
#pragma unroll
    for (int i = 0; i < 8; i++)
#pragma unroll
        for (int j = 0; j < 4; j++) accp[i][j] = 0ull;

    float4 pa[2], pb[2];
    {
        int k0 = 0;
#pragma unroll
        for (int s0 = 0; s0 < 2; s0++) {
            int slot = tid + s0 * 256;
            int r = slot >> 2;
            int kk = (slot & 3) << 2;
            float4 v = make_float4(0.f, 0.f, 0.f, 0.f);
            int gr = row0 + r;
            if (gr < M) v = *(const float4*)(A + (long long)gr * K + k0 + kk);
            pa[s0] = v;
        }
#pragma unroll
        for (int s0 = 0; s0 < 2; s0++) {
            int slot = tid + s0 * 256;
            int kk = slot >> 5;
            int c = (slot & 31) << 2;
            pb[s0] = *(const float4*)(B + (long long)(k0 + kk) * Nc + col0 + c);
        }
    }
    int nchunk = K >> 4;
    int buf = 0;
#pragma unroll
    for (int s0 = 0; s0 < 2; s0++) {
        int slot = tid + s0 * 256;
        int r = slot >> 2;
        int kk = (slot & 3) << 2;
        As[0][kk + 0][r] = pa[s0].x; As[0][kk + 1][r] = pa[s0].y;
        As[0][kk + 2][r] = pa[s0].z; As[0][kk + 3][r] = pa[s0].w;
        int kkb = slot >> 5;
        int c = (slot & 31) << 2;
        *(float4*)&Bs[0][kkb][c] = pb[s0];
    }
    __syncthreads();

    for (int ch = 0; ch < nchunk; ch++) {
        if (ch + 1 < nchunk) {
            int k0 = (ch + 1) << 4;
#pragma unroll
            for (int s0 = 0; s0 < 2; s0++) {
                int slot = tid + s0 * 256;
                int r = slot >> 2;
                int kk = (slot & 3) << 2;
                float4 v = make_float4(0.f, 0.f, 0.f, 0.f);
                int gr = row0 + r;
                if (gr < M) v = *(const float4*)(A + (long long)gr * K + k0 + kk);
                pa[s0] = v;
            }
#pragma unroll
            for (int s0 = 0; s0 < 2; s0++) {
                int slot = tid + s0 * 256;
                int kk = slot >> 5;
                int c = (slot & 31) << 2;
                pb[s0] = *(const float4*)(B + (long long)(k0 + kk) * Nc + col0 + c);
            }
        }
#pragma unroll
        for (int kk = 0; kk < 16; kk++) {
            float ra[8];
            *(float4*)&ra[0] = *(const float4*)&As[buf][kk][ty * 8];
            *(float4*)&ra[4] = *(const float4*)&As[buf][kk][ty * 8 + 4];
            const unsigned long long* bp = (const unsigned long long*)&Bs[buf][kk][tx * 8];
            unsigned long long rb0 = bp[0], rb1 = bp[1], rb2 = bp[2], rb3 = bp[3];
#pragma unroll
            for (int i = 0; i < 8; i++) {
                unsigned int au = __float_as_uint(ra[i]);
                unsigned long long rap;
                asm("mov.b64 %0, {%1, %1};" : "=l"(rap) : "r"(au));
                asm("fma.rn.f32x2 %0, %1, %2, %0;" : "+l"(accp[i][0]) : "l"(rap), "l"(rb0));
                asm("fma.rn.f32x2 %0, %1, %2, %0;" : "+l"(accp[i][1]) : "l"(rap), "l"(rb1));
                asm("fma.rn.f32x2 %0, %1, %2, %0;" : "+l"(accp[i][2]) : "l"(rap), "l"(rb2));
                asm("fma.rn.f32x2 %0, %1, %2, %0;" : "+l"(accp[i][3]) : "l"(rap), "l"(rb3));
            }
        }
        if (ch + 1 < nchunk) {
            int nb = buf ^ 1;
#pragma unroll
            for (int s0 = 0; s0 < 2; s0++) {
                int slot = tid + s0 * 256;
                int r = slot >> 2;
                int kk = (slot & 3) << 2;
                As[nb][kk + 0][r] = pa[s0].x; As[nb][kk + 1][r] = pa[s0].y;
                As[nb][kk + 2][r] = pa[s0].z; As[nb][kk + 3][r] = pa[s0].w;
                int kkb = slot >> 5;
                int c = (slot & 31) << 2;
                *(float4*)&Bs[nb][kkb][c] = pb[s0];
            }
            __syncthreads();
            buf = nb;
        }
    }
#pragma unroll
    for (int i = 0; i < 8; i++) {
        int gr = row0 + ty * 8 + i;
        if (gr < M) {
            float o[8];
#pragma unroll
            for (int j = 0; j < 4; j++) {
                unsigned int lo, hi;
                asm("mov.b64 {%0, %1}, %2;" : "=r"(lo), "=r"(hi) : "l"(accp[i][j]));
                o[2 * j]     = __uint_as_float(lo);
                o[2 * j + 1] = __uint_as_float(hi);
            }
            *(float4*)(C + (long long)gr * Nc + col0 + tx * 8)     = make_float4(o[0], o[1], o[2], o[3]);
            *(float4*)(C + (long long)gr * Nc + col0 + tx * 8 + 4) = make_float4(o[4], o[5], o[6], o[7]);
            uint4 w;
            __half2 p0 = __float22half2_rn(make_float2(o[0], o[1]));
            __half2 p1 = __float22half2_rn(make_float2(o[2], o[3]));
            __half2 p2 = __float22half2_rn(make_float2(o[4], o[5]));
            __half2 p3 = __float22half2_rn(make_float2(o[6], o[7]));
            w.x = *(unsigned int*)&p0; w.y = *(unsigned int*)&p1;
            w.z = *(unsigned int*)&p2; w.w = *(unsigned int*)&p3;
            *(uint4*)(Ch + (long long)gr * Nc + col0 + tx * 8) = w;
        }
    }
}

// ---------------- attention source/dest projections (fp32 h) ----------------
__global__ void __launch_bounds__(256) sd1_kernel(
    const float* __restrict__ as, const float* __restrict__ ad)
{
    int gw = (blockIdx.x * blockDim.x + threadIdx.x) >> 5;
    if (gw >= NN) return;
    int l = threadIdx.x & 31;
    int c0 = l << 3;
    const float* hr = g_h1 + (long long)gw * 256 + c0;
    float4 h0 = *(const float4*)hr;
    float4 h1v = *(const float4*)(hr + 4);
    float4 s0 = *(const float4*)(as + c0);
    float4 s1v = *(const float4*)(as + c0 + 4);
    float4 d0 = *(const float4*)(ad + c0);
    float4 d1v = *(const float4*)(ad + c0 + 4);
    float ps = h0.x*s0.x + h0.y*s0.y + h0.z*s0.z + h0.w*s0.w
             + h1v.x*s1v.x + h1v.y*s1v.y + h1v.z*s1v.z + h1v.w*s1v.w;
    float pd = h0.x*d0.x + h0.y*d0.y + h0.z*d0.z + h0.w*d0.w
             + h1v.x*d1v.x + h1v.y*d1v.y + h1v.z*d1v.z + h1v.w*d1v.w;
#pragma unroll
    for (int off = 4; off; off >>= 1) {
        ps += __shfl_xor_sync(0xffffffffu, ps, off);
        pd += __shfl_xor_sync(0xffffffffu, pd, off);
    }
    if ((l & 7) == 0) {
        g_s1[4 * gw + (l >> 3)] = ps;
        g_d1[4 * gw + (l >> 3)] = pd;
    }
}

__global__ void __launch_bounds__(256) sd2_kernel(
    const float* __restrict__ as, const float* __restrict__ ad)
{
    int gw = (blockIdx.x * blockDim.x + threadIdx.x) >> 5;
    if (gw >= NN) return;
    int l = threadIdx.x & 31;
    int c0 = l << 2;
    float4 h0 = *(const float4*)(g_h2 + (long long)gw * 128 + c0);
    float4 s0 = *(const float4*)(as + c0);
    float4 d0 = *(const float4*)(ad + c0);
    float ps = h0.x*s0.x + h0.y*s0.y + h0.z*s0.z + h0.w*s0.w;
    float pd = h0.x*d0.x + h0.y*d0.y + h0.z*d0.z + h0.w*d0.w;
#pragma unroll
    for (int off = 4; off; off >>= 1) {
        ps += __shfl_xor_sync(0xffffffffu, ps, off);
        pd += __shfl_xor_sync(0xffffffffu, pd, off);
    }
    if ((l & 7) == 0) {
        g_s2[4 * gw + (l >> 3)] = ps;
        g_d2[4 * gw + (l >> 3)] = pd;
    }
}

__device__ __forceinline__ void acc8_fp16(float* acc, uint4 v, float ex) {
    float2 f0 = __half22float2(*(__half2*)&v.x);
    float2 f1 = __half22float2(*(__half2*)&v.y);
    float2 f2 = __half22float2(*(__half2*)&v.z);
    float2 f3 = __half22float2(*(__half2*)&v.w);
    acc[0] += ex * f0.x; acc[1] += ex * f0.y;
    acc[2] += ex * f1.x; acc[3] += ex * f1.y;
    acc[4] += ex * f2.x; acc[5] += ex * f2.y;
    acc[6] += ex * f3.x; acc[7] += ex * f3.y;
}

// ---------------- GAT aggregation layer 1 (fp16 gather, fused BN+ELU) --------
__global__ void __launch_bounds__(256) agg1_kernel(
    const float* __restrict__ b1, const float* __restrict__ gm,
    const float* __restrict__ bt, const float* __restrict__ mn,
    const float* __restrict__ vr)
{
    int gw = (blockIdx.x * blockDim.x + threadIdx.x) >> 5;
    if (gw >= NN) return;
    int l = threadIdx.x & 31;
    int start = g_rowptr[gw], end = g_rowptr[gw + 1];
    int head = l >> 3;
    float dh = g_d1[4 * gw + head];
    int c0 = l << 3;
    float acc[8] = {0.f, 0.f, 0.f, 0.f, 0.f, 0.f, 0.f, 0.f};
    float den = 0.f;

    int j = start;
    for (; j + 4 <= end; j += 4) {
        int s0 = g_col[j], s1 = g_col[j + 1], s2 = g_col[j + 2], s3 = g_col[j + 3];
        float e0 = __expf(lrelu(g_s1[4 * s0 + head] + dh));
        float e1 = __expf(lrelu(g_s1[4 * s1 + head] + dh));
        float e2 = __expf(lrelu(g_s1[4 * s2 + head] + dh));
        float e3 = __expf(lrelu(g_s1[4 * s3 + head] + dh));
        uint4 v0 = *(const uint4*)(g_h1h + (long long)s0 * 256 + c0);
        uint4 v1 = *(const uint4*)(g_h1h + (long long)s1 * 256 + c0);
        uint4 v2 = *(const uint4*)(g_h1h + (long long)s2 * 256 + c0);
        uint4 v3 = *(const uint4*)(g_h1h + (long long)s3 * 256 + c0);
        den += (e0 + e1) + (e2 + e3);
        acc8_fp16(acc, v0, e0);
        acc8_fp16(acc, v1, e1);
        acc8_fp16(acc, v2, e2);
        acc8_fp16(acc, v3, e3);
    }
    for (; j < end; j++) {
        int s = g_col[j];
        float ex = __expf(lrelu(g_s1[4 * s + head] + dh));
        den += ex;
        uint4 v = *(const uint4*)(g_h1h + (long long)s * 256 + c0);
        acc8_fp16(acc, v, ex);
    }
    float inv = 1.f / (den + 1e-16f);
    float out[8];
#pragma unroll
    for (int i = 0; i < 8; i++) {
        int c = c0 + i;
        float v = acc[i] * inv + b1[c];
        v = (v - mn[c]) * rsqrtf(vr[c] + EPS_BN) * gm[c] + bt[c];
        out[i] = v > 0.f ? v : expm1f(v);
    }
    float4* op = (float4*)(g_out1 + (long long)gw * 256 + c0);
    op[0] = make_float4(out[0], out[1], out[2], out[3]);
    op[1] = make_float4(out[4], out[5], out[6], out[7]);
}

// ------------ GAT aggregation layer 2 (fp16 gather, BN+ELU+FC head) ----------
__global__ void __launch_bounds__(256) agg2_kernel(
    const float* __restrict__ b2, const float* __restrict__ gm,
    const float* __restrict__ bt, const float* __restrict__ mn,
    const float* __restrict__ vr, const float* __restrict__ fcW,
    const float* __restrict__ fcb, float* __restrict__ out)
{
    int gw = (blockIdx.x * blockDim.x + threadIdx.x) >> 5;
    if (gw >= NN) return;
    int l = threadIdx.x & 31;
    int start = g_rowptr[gw], end = g_rowptr[gw + 1];
    int head = l >> 3;
    float dh = g_d2[4 * gw + head];
    int c0 = l << 2;
    float acc[4] = {0.f, 0.f, 0.f, 0.f};
    float den = 0.f;

    int j = start;
    for (; j + 4 <= end; j += 4) {
        int s0 = g_col[j], s1 = g_col[j + 1], s2 = g_col[j + 2], s3 = g_col[j + 3];
        float e0 = __expf(lrelu(g_s2[4 * s0 + head] + dh));
        float e1 = __expf(lrelu(g_s2[4 * s1 + head] + dh));
        float e2 = __expf(lrelu(g_s2[4 * s2 + head] + dh));
        float e3 = __expf(lrelu(g_s2[4 * s3 + head] + dh));
        uint2 v0 = *(const uint2*)(g_h2h + (long long)s0 * 128 + c0);
        uint2 v1 = *(const uint2*)(g_h2h + (long long)s1 * 128 + c0);
        uint2 v2 = *(const uint2*)(g_h2h + (long long)s2 * 128 + c0);
        uint2 v3 = *(const uint2*)(g_h2h + (long long)s3 * 128 + c0);
        den += (e0 + e1) + (e2 + e3);
        float2 f;
        f = __half22float2(*(__half2*)&v0.x); acc[0] += e0*f.x; acc[1] += e0*f.y;
        f = __half22float2(*(__half2*)&v0.y); acc[2] += e0*f.x; acc[3] += e0*f.y;
        f = __half22float2(*(__half2*)&v1.x); acc[0] += e1*f.x; acc[1] += e1*f.y;
        f = __half22float2(*(__half2*)&v1.y); acc[2] += e1*f.x; acc[3] += e1*f.y;
        f = __half22float2(*(__half2*)&v2.x); acc[0] += e2*f.x; acc[1] += e2*f.y;
        f = __half22float2(*(__half2*)&v2.y); acc[2] += e2*f.x; acc[3] += e2*f.y;
        f = __half22float2(*(__half2*)&v3.x); acc[0] += e3*f.x; acc[1] += e3*f.y;
        f = __half22float2(*(__half2*)&v3.y); acc[2] += e3*f.x; acc[3] += e3*f.y;
    }
    for (; j < end; j++) {
        int s = g_col[j];
        float ex = __expf(lrelu(g_s2[4 * s + head] + dh));
        den += ex;
        uint2 v0 = *(const uint2*)(g_h2h + (long long)s * 128 + c0);
        float2 f;
        f = __half22float2(*(__half2*)&v0.x); acc[0] += ex*f.x; acc[1] += ex*f.y;
        f = __half22float2(*(__half2*)&v0.y); acc[2] += ex*f.x; acc[3] += ex*f.y;
    }
    float inv = 1.f / (den + 1e-16f);
    float r = 0.f;
#pragma unroll
    for (int i = 0; i < 4; i++) {
        int c = c0 + i;
        float v = acc[i] * inv + b2[c];
        v = (v - mn[c]) * rsqrtf(vr[c] + EPS_BN) * gm[c] + bt[c];
        v = v > 0.f ? v : expm1f(v);
        r += v * fcW[c];
    }
#pragma unroll
    for (int off = 16; off; off >>= 1) r += __shfl_xor_sync(0xffffffffu, r, off);
    if (l == 0) out[gw] = r + fcb[0];
}

// ---------------- launch ----------------
extern "C" void kernel_launch(void* const* d_in, const int* in_sizes, int n_in,
                              void* d_out, int out_size) {
    const float* x    = (const float*)d_in[0];
    const void*  eidx = d_in[1];
    const float* W1   = (const float*)d_in[2];
    const float* a1s  = (const float*)d_in[3];
    const float* a1d  = (const float*)d_in[4];
    const float* b1   = (const float*)d_in[5];
    const float* g1   = (const float*)d_in[6];
    const float* be1  = (const float*)d_in[7];
    const float* m1   = (const float*)d_in[8];
    const float* v1   = (const float*)d_in[9];
    const float* W2   = (const float*)d_in[10];
    const float* a2s  = (const float*)d_in[11];
    const float* a2d  = (const float*)d_in[12];
    const float* b2   = (const float*)d_in[13];
    const float* g2   = (const float*)d_in[14];
    const float* be2  = (const float*)d_in[15];
    const float* m2   = (const float*)d_in[16];
    const float* v2   = (const float*)d_in[17];
    const float* fcW  = (const float*)d_in[18];
    const float* fcb  = (const float*)d_in[19];

    int E  = in_sizes[1] / 2;
    int EP = E + NN;

    float *h1p, *out1p, *h2p;
    __half *h1hp, *h2hp;
    cudaGetSymbolAddress((void**)&h1p,   g_h1);
    cudaGetSymbolAddress((void**)&out1p, g_out1);
    cudaGetSymbolAddress((void**)&h2p,   g_h2);
    cudaGetSymbolAddress((void**)&h1hp,  g_h1h);
    cudaGetSymbolAddress((void**)&h2hp,  g_h2h);

    const int TPB = 256;
    int warp_blocks = (NN * 32 + TPB - 1) / TPB;
    int scan_blocks = (NN + 1023) / 1024;

    detect_kernel<<<1, 256>>>((const int*)eidx);
    zero_kernel<<<(NN + TPB - 1) / TPB, TPB>>>();
    count_kernel<<<(EP + TPB - 1) / TPB, TPB>>>(eidx, E, EP);
    scan_block_kernel<<<scan_blocks, 1024>>>();
    scan_sums_kernel<<<1, 64>>>(scan_blocks);
    scan_add_kernel<<<scan_blocks, 1024>>>();
    scatter_kernel<<<(EP + TPB - 1) / TPB, TPB>>>(eidx, E, EP);

    // Layer 1
    gemm_kernel<<<dim3(2, (NN + 127) / 128), 256>>>(x, W1, h1p, h1hp, NN, 128, 256);
    sd1_kernel<<<warp_blocks, TPB>>>(a1s, a1d);
    agg1_kernel<<<warp_blocks, TPB>>>(b1, g1, be1, m1, v1);

    // Layer 2
    gemm_kernel<<<dim3(1, (NN + 127) / 128), 256>>>(out1p, W2, h2p, h2hp, NN, 256, 128);
    sd2_kernel<<<warp_blocks, TPB>>>(a2s, a2d);
    agg2_kernel<<<warp_blocks, TPB>>>(b2, g2, be2, m2, v2, fcW, fcb, (float*)d_out);
}